// round 16
// baseline (speedup 1.0000x reference)
#include <cuda_runtime.h>
#include <cuda_bf16.h>
#include <cstdint>

#define FBANK_MEAN_F 15.41663f

// ---------------- device scratch (static, no allocation) ----------------
__device__ float g_cbn[1024 * 256];
__device__ float g_Ap[256 * 256];
__device__ float g_Ht[1024 * 256];             // code-major fp32 (refinement)
__device__ __nv_bfloat16 g_Bhi[1024 * 256];    // code-major: Bhi[n][p]
__device__ __nv_bfloat16 g_Blo[1024 * 256];    // residual
__device__ __nv_bfloat16 g_Xhi[51200 * 256];   // token-major (X - MEAN), hi
__device__ __nv_bfloat16 g_Xlo[51200 * 256];   // residual
__device__ int2  g_cand[51200];                // approx top-2 per token
__device__ float g_pcs[16][256];               // partial csum (proj)
__device__ float g_pwb[16][256];               // partial wsum (conv)
__device__ int   g_wide;

__device__ __forceinline__ uint32_t smem_u32(const void* p) {
    uint32_t a;
    asm("{ .reg .u64 t; cvta.to.shared.u64 t, %1; cvt.u32.u64 %0, t; }" : "=r"(a) : "l"(p));
    return a;
}
#define LDSM4(r, addr) \
    asm volatile("ldmatrix.sync.aligned.m8n8.x4.shared.b16 {%0,%1,%2,%3}, [%4];" \
        : "=r"((r)[0]), "=r"((r)[1]), "=r"((r)[2]), "=r"((r)[3]) : "r"(addr))
#define MMA16816(c, a, b0, b1) \
    asm volatile("mma.sync.aligned.m16n8k16.row.col.f32.bf16.bf16.f32 " \
        "{%0,%1,%2,%3},{%4,%5,%6,%7},{%8,%9},{%0,%1,%2,%3};" \
        : "+f"((c)[0]), "+f"((c)[1]), "+f"((c)[2]), "+f"((c)[3]) \
        : "r"((a)[0]), "r"((a)[1]), "r"((a)[2]), "r"((a)[3]), "r"(b0), "r"(b1))
#define CP16(dst, src) \
    asm volatile("cp.async.cg.shared.global [%0], [%1], 16;" :: "r"(dst), "l"(src) : "memory")
#define CP_COMMIT() asm volatile("cp.async.commit_group;" ::: "memory")
#define CP_WAIT1()  asm volatile("cp.async.wait_group 1;" ::: "memory")
#define CP_WAIT0()  asm volatile("cp.async.wait_group 0;" ::: "memory")

// block-wide sign of sum(|A|-|B|) over 256 elems: 1 if A is proj (bigger RMS)
__device__ __forceinline__ int block_swap_probe(const float* bufA, const float* bufB,
                                                int tid, float* red8, int* s_swap) {
    float d = fabsf(bufA[tid]) - fabsf(bufB[tid]);
    #pragma unroll
    for (int o = 16; o; o >>= 1) d += __shfl_down_sync(0xffffffffu, d, o);
    if ((tid & 31) == 0) red8[tid >> 5] = d;
    __syncthreads();
    if (tid == 0) {
        float s = 0.f;
        #pragma unroll
        for (int i = 0; i < 8; i++) s += red8[i];
        *s_swap = (s > 0.f) ? 1 : 0;
    }
    __syncthreads();
    return *s_swap;
}

// ---------------- k_pre: probe + cbn + sums1 + xsplit (fused) ----
__global__ void k_pre(const float* __restrict__ cb,
                      const float* __restrict__ bufA, const float* __restrict__ bufB,
                      const float* __restrict__ xs,
                      const unsigned* __restrict__ ilens_raw) {
    int bid = blockIdx.x;
    int tid = threadIdx.x;
    if (bid < 1024) {                       // codebook l2norm
        int k = bid;
        float v = cb[k * 256 + tid];
        float s = v * v;
        #pragma unroll
        for (int o = 16; o; o >>= 1) s += __shfl_down_sync(0xffffffffu, s, o);
        __shared__ float red[8];
        if ((tid & 31) == 0) red[tid >> 5] = s;
        __syncthreads();
        if (tid == 0) {
            float tot = 0.f;
            #pragma unroll
            for (int i = 0; i < 8; i++) tot += red[i];
            red[0] = rsqrtf(tot + 1e-12f);
        }
        __syncthreads();
        g_cbn[k * 256 + tid] = v * red[0];
    } else if (bid < 1040) {                // column-sum partials (local swap)
        __shared__ float red[8];
        __shared__ int s_swap;
        int sw = block_swap_probe(bufA, bufB, tid, red, &s_swap);
        const float* proj  = sw ? bufA : bufB;
        const float* convw = sw ? bufB : bufA;
        int r = bid - 1024, c0 = r * 32;
        float s = 0.f, w = 0.f;
        #pragma unroll 8
        for (int c = c0; c < c0 + 32; c++) { s += proj[c * 256 + tid]; w += convw[c * 256 + tid]; }
        g_pcs[r][tid] = s;
        g_pwb[r][tid] = w;
    } else if (bid < 13840) {               // X gather + (X-MEAN) bf16 hi/lo split
        int n = (bid - 1040) * 4 + (tid >> 6);
        int t64 = tid & 63;
        int j = t64 * 4;
        int b = n / 1600;
        int rem = n - b * 1600;
        int tp = rem >> 3, fp = rem & 7;
        int r = j >> 4, c = j & 15;
        const float4 v = *(const float4*)(xs + ((size_t)b * 3200 + tp * 16 + r) * 128 + fp * 16 + c);
        float xv[4] = { v.x - FBANK_MEAN_F, v.y - FBANK_MEAN_F,
                        v.z - FBANK_MEAN_F, v.w - FBANK_MEAN_F };
        __nv_bfloat16 hi[4], lo[4];
        #pragma unroll
        for (int i = 0; i < 4; i++) {
            hi[i] = __float2bfloat16(xv[i]);
            lo[i] = __float2bfloat16(xv[i] - __bfloat162float(hi[i]));
        }
        *(uint2*)&g_Xhi[(size_t)n * 256 + j] = *(uint2*)hi;
        *(uint2*)&g_Xlo[(size_t)n * 256 + j] = *(uint2*)lo;
    } else {
        if (tid == 0) g_wide = (ilens_raw[1] == 0u) ? 1 : 0;
    }
}

// ---------------- gemmA: A' = Wf^T P - wbar csum^T ----------------
__global__ void k_gemmA(const float* __restrict__ bufA, const float* __restrict__ bufB) {
    __shared__ float Ws[32][16], Ps[32][16];
    __shared__ float s_wbar[16], s_csum[16];
    __shared__ float red[8];
    __shared__ int s_swap;
    int tx = threadIdx.x, ty = threadIdx.y;
    int tid = ty * 16 + tx;
    int p0 = blockIdx.y * 16, q0 = blockIdx.x * 16;
    int sw = block_swap_probe(bufA, bufB, tid, red, &s_swap);
    const float* proj  = sw ? bufA : bufB;
    const float* convw = sw ? bufB : bufA;
    if (tid < 16) {
        float s = 0.f;
        #pragma unroll
        for (int r = 0; r < 16; r++) s += g_pcs[r][q0 + tid];
        s_csum[tid] = s;
    } else if (tid < 32) {
        int i = tid - 16;
        float w = 0.f;
        #pragma unroll
        for (int r = 0; r < 16; r++) w += g_pwb[r][p0 + i];
        s_wbar[i] = w * (1.0f / 512.0f);
    }
    __syncthreads();
    float acc = 0.f;
    for (int c0 = 0; c0 < 512; c0 += 32) {
        #pragma unroll
        for (int l = 0; l < 2; l++) {
            Ws[l * 16 + ty][tx] = convw[(c0 + l * 16 + ty) * 256 + p0 + tx];
            Ps[l * 16 + ty][tx] = proj[(c0 + l * 16 + ty) * 256 + q0 + tx];
        }
        __syncthreads();
        #pragma unroll
        for (int k = 0; k < 32; k++) acc += Ws[k][ty] * Ps[k][tx];
        __syncthreads();
    }
    g_Ap[(p0 + ty) * 256 + q0 + tx] = acc - s_wbar[ty] * s_csum[tx];
}

// ---------------- gemmH: H = A' cbn^T ; fp32 transposed + bf16 hi/lo ----------
__global__ void k_gemmH() {
    __shared__ float As[32][17], Bs[32][17];
    int tid = threadIdx.x;
    int tx = tid & 15, ty = tid >> 4;
    int k0 = blockIdx.x * 16, p0 = blockIdx.y * 16;
    int rr = tid >> 5, cc = tid & 31;
    float acc = 0.f;
    for (int q0 = 0; q0 < 256; q0 += 32) {
        #pragma unroll
        for (int l = 0; l < 2; l++) {
            As[cc][l * 8 + rr] = g_Ap[(p0 + l * 8 + rr) * 256 + q0 + cc];
            Bs[cc][l * 8 + rr] = g_cbn[(k0 + l * 8 + rr) * 256 + q0 + cc];
        }
        __syncthreads();
        #pragma unroll
        for (int q = 0; q < 32; q++) acc += As[q][ty] * Bs[q][tx];
        __syncthreads();
    }
    int p = p0 + ty, k = k0 + tx;
    g_Ht[k * 256 + p] = acc;
    __nv_bfloat16 hi = __float2bfloat16(acc);
    __nv_bfloat16 lo = __float2bfloat16(acc - __bfloat162float(hi));
    g_Bhi[k * 256 + p] = hi;
    g_Blo[k * 256 + p] = lo;
}

// ---------------- main: HMMA bf16x3 GEMM + approx top-2 (16 warps, 2D tile) ---
#define XPAD 264
#define XV_BYTES 67584
#define BV_BYTES 16896
#define BBUF_BYTES 33792
#define SM_B0 135168
#define SM_TOTAL 202752

struct Top2 { float v1, v2; int i1, i2; };
__device__ __forceinline__ void t2_upd(Top2& t, float s, int idx) {
    if (s > t.v1 || (s == t.v1 && idx < t.i1)) { t.v2 = t.v1; t.i2 = t.i1; t.v1 = s; t.i1 = idx; }
    else if (s > t.v2 || (s == t.v2 && idx < t.i2)) { t.v2 = s; t.i2 = idx; }
}
__device__ __forceinline__ void t2_merge(Top2& t, float ov1, int oi1, float ov2, int oi2) {
    if (ov1 > t.v1 || (ov1 == t.v1 && oi1 < t.i1)) {
        if (t.v1 > ov2 || (t.v1 == ov2 && t.i1 < oi2)) { t.v2 = t.v1; t.i2 = t.i1; }
        else { t.v2 = ov2; t.i2 = oi2; }
        t.v1 = ov1; t.i1 = oi1;
    } else {
        if (ov1 > t.v2 || (ov1 == t.v2 && oi1 < t.i2)) { t.v2 = ov1; t.i2 = oi1; }
    }
}

__global__ __launch_bounds__(512, 1) void k_main(int2* __restrict__ cand) {
    extern __shared__ char dsm[];
    uint32_t sb = smem_u32(dsm);
    int tid = threadIdx.x;
    int l = tid & 31, w = tid >> 5;           // 16 warps
    int wm = w & 7, wn = w >> 3;              // 8 M-groups x 2 N-groups
    int m0 = blockIdx.x * 128;

    // ---- X fill: 8192 16B granules (hi+lo) ----
    #pragma unroll
    for (int i = 0; i < 16; i++) {
        int id = i * 512 + tid;
        int ver = id >> 12, rem = id & 4095;
        int row = rem >> 5, g = rem & 31;
        const __nv_bfloat16* src = (ver ? g_Xlo : g_Xhi) + (size_t)(m0 + row) * 256 + g * 8;
        CP16(sb + ver * XV_BYTES + row * 528 + g * 16, src);
    }
    // ---- B chunk 0: 2048 granules ----
    {
        #pragma unroll
        for (int i = 0; i < 4; i++) {
            int id = i * 512 + tid;
            int ver = id >> 10, rem = id & 1023;
            int row = rem >> 5, g = rem & 31;
            const __nv_bfloat16* src = (ver ? g_Blo : g_Bhi) + (size_t)row * 256 + g * 8;
            CP16(sb + SM_B0 + ver * BV_BYTES + row * 528 + g * 16, src);
        }
    }
    CP_COMMIT();

    uint32_t a_off = (uint32_t)(((wm * 16 + (l & 7) + ((l >> 3) & 1) * 8) * XPAD
                                 + (l >> 4) * 8) * 2);
    uint32_t b_off = (uint32_t)((((l & 7) + ((l >> 4) & 1) * 8 + wn * 16) * XPAD
                                 + ((l >> 3) & 1) * 8) * 2);

    Top2 t0 = { -1e30f, -1e30f, 0, 0 };
    Top2 t1 = { -1e30f, -1e30f, 0, 0 };

    for (int c = 0; c < 32; c++) {
        __syncthreads();
        if (c + 1 < 32) {
            uint32_t dst = sb + SM_B0 + ((c + 1) & 1) * BBUF_BYTES;
            #pragma unroll
            for (int i = 0; i < 4; i++) {
                int id = i * 512 + tid;
                int ver = id >> 10, rem = id & 1023;
                int row = rem >> 5, g = rem & 31;
                const __nv_bfloat16* src = (ver ? g_Blo : g_Bhi)
                    + (size_t)((c + 1) * 32 + row) * 256 + g * 8;
                CP16(dst + ver * BV_BYTES + row * 528 + g * 16, src);
            }
            CP_COMMIT();
            CP_WAIT1();
        } else {
            CP_WAIT0();
        }
        __syncthreads();

        uint32_t bhiB = sb + SM_B0 + (c & 1) * BBUF_BYTES;
        uint32_t bloB = bhiB + BV_BYTES;

        float acc[2][4];
        #pragma unroll
        for (int nt = 0; nt < 2; nt++)
            #pragma unroll
            for (int i = 0; i < 4; i++) acc[nt][i] = 0.f;

        #pragma unroll
        for (int kk = 0; kk < 16; kk++) {
            uint32_t ko = kk * 32;
            uint32_t ahi[4], alo[4], bh[4], bl[4];
            LDSM4(ahi, sb + a_off + ko);
            LDSM4(alo, sb + XV_BYTES + a_off + ko);
            LDSM4(bh, bhiB + b_off + ko);
            LDSM4(bl, bloB + b_off + ko);
            MMA16816(acc[0], ahi, bh[0], bh[1]);
            MMA16816(acc[1], ahi, bh[2], bh[3]);
            MMA16816(acc[0], ahi, bl[0], bl[1]);
            MMA16816(acc[1], ahi, bl[2], bl[3]);
            MMA16816(acc[0], alo, bh[0], bh[1]);
            MMA16816(acc[1], alo, bh[2], bh[3]);
        }

        #pragma unroll
        for (int nt = 0; nt < 2; nt++) {
            int g0 = c * 32 + wn * 16 + nt * 8 + 2 * (l & 3);
            t2_upd(t0, acc[nt][0], g0);
            t2_upd(t0, acc[nt][1], g0 + 1);
            t2_upd(t1, acc[nt][2], g0);
            t2_upd(t1, acc[nt][3], g0 + 1);
        }
    }

    // quad merge within warp (lanes sharing rows own disjoint codes)
    #pragma unroll
    for (int off = 1; off <= 2; off <<= 1) {
        float ov1 = __shfl_xor_sync(0xffffffffu, t0.v1, off);
        int   oi1 = __shfl_xor_sync(0xffffffffu, t0.i1, off);
        float ov2 = __shfl_xor_sync(0xffffffffu, t0.v2, off);
        int   oi2 = __shfl_xor_sync(0xffffffffu, t0.i2, off);
        t2_merge(t0, ov1, oi1, ov2, oi2);
        ov1 = __shfl_xor_sync(0xffffffffu, t1.v1, off);
        oi1 = __shfl_xor_sync(0xffffffffu, t1.i1, off);
        ov2 = __shfl_xor_sync(0xffffffffu, t1.v2, off);
        oi2 = __shfl_xor_sync(0xffffffffu, t1.i2, off);
        t2_merge(t1, ov1, oi1, ov2, oi2);
    }

    // cross-N-half merge through smem (X region is dead now)
    float* mv1 = (float*)dsm;
    float* mv2 = (float*)(dsm + 512);
    int*   mi1 = (int*)(dsm + 1024);
    int*   mi2 = (int*)(dsm + 1536);
    __syncthreads();
    if (wn == 1 && (l & 3) == 0) {
        int r0 = wm * 16 + (l >> 2);
        mv1[r0] = t0.v1; mv2[r0] = t0.v2; mi1[r0] = t0.i1; mi2[r0] = t0.i2;
        mv1[r0 + 8] = t1.v1; mv2[r0 + 8] = t1.v2; mi1[r0 + 8] = t1.i1; mi2[r0 + 8] = t1.i2;
    }
    __syncthreads();
    if (wn == 0 && (l & 3) == 0) {
        int r0 = wm * 16 + (l >> 2);
        t2_merge(t0, mv1[r0], mi1[r0], mv2[r0], mi2[r0]);
        t2_merge(t1, mv1[r0 + 8], mi1[r0 + 8], mv2[r0 + 8], mi2[r0 + 8]);
        cand[m0 + r0]     = make_int2(t0.i1, t0.i2);
        cand[m0 + r0 + 8] = make_int2(t1.i1, t1.i2);
    }
}

// ---------------- exact fp32 refinement: warp per token ----------------
__global__ __launch_bounds__(256) void k_refine(const float* __restrict__ xs,
                                                float* __restrict__ out) {
    int wp = threadIdx.x >> 5, l = threadIdx.x & 31;
    int n = blockIdx.x * 8 + wp;
    int b = n / 1600;
    int rem = n - b * 1600;
    int tp = rem >> 3, fp = rem & 7;
    int j0 = l * 8;
    int r = j0 >> 4, c = j0 & 15;
    const float* xb = xs + ((size_t)b * 3200 + tp * 16 + r) * 128 + fp * 16 + c;
    float4 xa = *(const float4*)xb;
    float4 xc = *(const float4*)(xb + 4);
    float xm[8] = { xa.x - FBANK_MEAN_F, xa.y - FBANK_MEAN_F, xa.z - FBANK_MEAN_F,
                    xa.w - FBANK_MEAN_F, xc.x - FBANK_MEAN_F, xc.y - FBANK_MEAN_F,
                    xc.z - FBANK_MEAN_F, xc.w - FBANK_MEAN_F };
    int2 cd = g_cand[n];
    const float* h0 = g_Ht + (size_t)cd.x * 256 + j0;
    const float* h1 = g_Ht + (size_t)cd.y * 256 + j0;
    float s0 = 0.f, s1 = 0.f;
    #pragma unroll
    for (int i = 0; i < 8; i++) { s0 += xm[i] * h0[i]; s1 += xm[i] * h1[i]; }
    #pragma unroll
    for (int off = 16; off; off >>= 1) {
        s0 += __shfl_down_sync(0xffffffffu, s0, off);
        s1 += __shfl_down_sync(0xffffffffu, s1, off);
    }
    if (l == 0) {
        int best = (s1 > s0 || (s1 == s0 && cd.y < cd.x)) ? cd.y : cd.x;
        out[n] = (float)best;
    }
}

// embed_len[b] = 8 * min(floor(ilens[b]/16), 200)
__global__ void k_len(const unsigned* __restrict__ ilens_raw, float* __restrict__ out,
                      int out_size) {
    int t = threadIdx.x;
    if (t < 32 && (51200 + t) < out_size) {
        int il = g_wide ? (int)ilens_raw[2 * t] : (int)ilens_raw[t];
        int full = il >> 4;
        if (full > 200) full = 200;
        out[51200 + t] = (float)(full << 3);
    }
}

// ---------------- launch ----------------
extern "C" void kernel_launch(void* const* d_in, const int* in_sizes, int n_in,
                              void* d_out, int out_size) {
    const float*    xs    = 0;
    const unsigned* ilens = 0;
    const float*    bufA  = 0;
    const float*    bufB  = 0;
    const float*    cb    = 0;
    for (int i = 0; i < n_in; i++) {
        int s = in_sizes[i];
        if (s == 13107200)      xs = (const float*)d_in[i];
        else if (s == 262144)   cb = (const float*)d_in[i];
        else if (s == 131072) { if (!bufA) bufA = (const float*)d_in[i];
                                else       bufB = (const float*)d_in[i]; }
        else if (s == 32 || s == 64) ilens = (const unsigned*)d_in[i];
    }

    int2* cand;
    cudaGetSymbolAddress((void**)&cand, g_cand);

    k_pre<<<13841, 256>>>(cb, bufA, bufB, xs, ilens);                 // 1
    k_gemmA<<<dim3(16, 16), dim3(16, 16)>>>(bufA, bufB);              // 2
    k_gemmH<<<dim3(64, 16), 256>>>();                                 // 3
    cudaFuncSetAttribute(k_main, cudaFuncAttributeMaxDynamicSharedMemorySize, SM_TOTAL);
    k_main<<<400, 512, SM_TOTAL>>>(cand);                             // 4 <- profiled
    k_refine<<<6400, 256>>>(xs, (float*)d_out);                       // 5
    k_len<<<1, 32>>>(ilens, (float*)d_out, out_size);                 // 6
}